// round 12
// baseline (speedup 1.0000x reference)
#include <cuda_runtime.h>
#include <cuda_bf16.h>
#include <math.h>

// ---------------- static scratch (no allocations allowed) ----------------
// sizes: B=64 T=16 H=W=64 C=16 -> BT=1024
__device__ float g_w1t[256 * 64];          // conv1 weights, k-major  (k = dy*64+dx*16+ci)
__device__ float g_w2t[1024 * 256];        // conv2 weights, k-major  (k = dy*256+dx*64+ci)
__device__ float g_h1[1024 * 256 * 64];    // conv1 out, (bt,oh,ow,64) channels-last, post LN+gelu
__device__ float g_c2[16384 * 256];        // conv2 out rows; LN+gelu applied in place
__device__ float g_emb[1024 * 512];        // fc out (bt, 512)
__device__ float g_gates[64 * 6];          // gate weights per batch

typedef unsigned long long u64;

__device__ __forceinline__ float gelu_f(float v) {
    return 0.5f * v * (1.0f + erff(v * 0.70710678118654752440f));
}

__device__ __forceinline__ u64 fma2(u64 a, u64 b, u64 c) {
    asm("fma.rn.f32x2 %0, %1, %2, %0;" : "+l"(c) : "l"(a), "l"(b));
    return c;
}
__device__ __forceinline__ float2 unpack2(u64 v) {
    float2 r;
    asm("mov.b64 {%0, %1}, %2;" : "=f"(r.x), "=f"(r.y) : "l"(v));
    return r;
}

// ---------------- weight re-layout (k-major for GEMM B tiles) ----------------
__global__ void prep_weights(const float* __restrict__ w1, const float* __restrict__ w2) {
    int i = blockIdx.x * 256 + threadIdx.x;
    if (i < 16384) {                 // w1: (co,ci,dy,dx) -> w1t[k*64+co], k=(dy,dx,ci)
        int k = i >> 6, co = i & 63;
        int dy = k >> 6, dx = (k >> 4) & 3, ci = k & 15;
        g_w1t[i] = w1[((co * 16 + ci) * 4 + dy) * 4 + dx];
    }
    if (i < 262144) {                // w2: (co,ci,dy,dx) -> w2t[k*256+co], k=(dy,dx,ci)
        int k = i >> 8, co = i & 255;
        int dy = k >> 8, dx = (k >> 6) & 3, ci = k & 63;
        g_w2t[i] = w2[((co * 64 + ci) * 4 + dy) * 4 + dx];
    }
}

// =======================================================================
// conv1 implicit GEMM with packed f32x2: M=262144, N=64, K=256
// block 128m x 64n, 256 thr, per-thread 2 m-pairs x 8 n.
// As[k][m] transposed (m-pairs contiguous); Bs duplicated pairs.
// epilogue: bias + LN(64) + gelu fused.
// =======================================================================
__global__ __launch_bounds__(256) void conv1_kernel(
    const float* __restrict__ x, const float* __restrict__ bias,
    const float* __restrict__ lng, const float* __restrict__ lnb)
{
    __shared__ float As[32][132];
    __shared__ float Bs[32][132];
    __shared__ float s_sum[128];
    __shared__ float s_ssum[128];
    const int tid = threadIdx.x;
    const int tm = tid & 31;            // m pair groups: pairs at 2tm, 2tm+64
    const int tn = tid >> 5;            // n cols tn*8 .. +7
    const int ml = tid >> 1;            // A loader row (0..127)
    const int q  = tid & 1;             // A loader half of 32 k
    const int brow = tid >> 3;          // B loader k row (0..31)
    const int bq   = tid & 7;           // B loader n-octet
    const int m0 = blockIdx.x * 128;
    const int mg = m0 + ml;
    const int bt = mg >> 8, oh = (mg >> 4) & 15, ow = mg & 15;
    const float4* x4 = reinterpret_cast<const float4*>(x);
    const float4* w4 = reinterpret_cast<const float4*>(g_w1t);

    u64 acc[2][8];
#pragma unroll
    for (int i = 0; i < 2; i++)
#pragma unroll
        for (int n = 0; n < 8; n++) acc[i][n] = 0ull;

    float4 ra[4], rb[2];
    {   // prefetch chunk 0 (dy=0, dx-half=0)
        int ab = ((bt * 64 + oh * 4 + 0) * 64 + ow * 4 + 0) * 4 + q * 4;
#pragma unroll
        for (int v = 0; v < 4; v++) ra[v] = x4[ab + v];
        int bb = (0 * 32 + brow) * 16 + bq * 2;
        rb[0] = w4[bb]; rb[1] = w4[bb + 1];
    }
#pragma unroll 1
    for (int c = 0; c < 8; c++) {
        __syncthreads();
#pragma unroll
        for (int v = 0; v < 4; v++) {        // A transposed scalar stores
            int k = q * 16 + v * 4;
            As[k + 0][ml] = ra[v].x; As[k + 1][ml] = ra[v].y;
            As[k + 2][ml] = ra[v].z; As[k + 3][ml] = ra[v].w;
        }
#pragma unroll
        for (int v = 0; v < 2; v++) {        // B duplicated-pair stores
            int nn = bq * 8 + v * 4;
            *reinterpret_cast<float4*>(&Bs[brow][nn * 2])     = make_float4(rb[v].x, rb[v].x, rb[v].y, rb[v].y);
            *reinterpret_cast<float4*>(&Bs[brow][nn * 2 + 4]) = make_float4(rb[v].z, rb[v].z, rb[v].w, rb[v].w);
        }
        __syncthreads();
        if (c + 1 < 8) {
            int cn = c + 1, dy = cn >> 1, dxh = cn & 1;
            int ab = ((bt * 64 + oh * 4 + dy) * 64 + ow * 4 + dxh * 2) * 4 + q * 4;
#pragma unroll
            for (int v = 0; v < 4; v++) ra[v] = x4[ab + v];
            int bb = (cn * 32 + brow) * 16 + bq * 2;
            rb[0] = w4[bb]; rb[1] = w4[bb + 1];
        }
#pragma unroll
        for (int kk = 0; kk < 32; kk++) {
            u64 a0 = *reinterpret_cast<const u64*>(&As[kk][2 * tm]);
            u64 a1 = *reinterpret_cast<const u64*>(&As[kk][2 * tm + 64]);
            ulonglong2 t0 = *reinterpret_cast<const ulonglong2*>(&Bs[kk][tn * 16 + 0]);
            ulonglong2 t1 = *reinterpret_cast<const ulonglong2*>(&Bs[kk][tn * 16 + 4]);
            ulonglong2 t2 = *reinterpret_cast<const ulonglong2*>(&Bs[kk][tn * 16 + 8]);
            ulonglong2 t3 = *reinterpret_cast<const ulonglong2*>(&Bs[kk][tn * 16 + 12]);
            acc[0][0] = fma2(a0, t0.x, acc[0][0]); acc[1][0] = fma2(a1, t0.x, acc[1][0]);
            acc[0][1] = fma2(a0, t0.y, acc[0][1]); acc[1][1] = fma2(a1, t0.y, acc[1][1]);
            acc[0][2] = fma2(a0, t1.x, acc[0][2]); acc[1][2] = fma2(a1, t1.x, acc[1][2]);
            acc[0][3] = fma2(a0, t1.y, acc[0][3]); acc[1][3] = fma2(a1, t1.y, acc[1][3]);
            acc[0][4] = fma2(a0, t2.x, acc[0][4]); acc[1][4] = fma2(a1, t2.x, acc[1][4]);
            acc[0][5] = fma2(a0, t2.y, acc[0][5]); acc[1][5] = fma2(a1, t2.y, acc[1][5]);
            acc[0][6] = fma2(a0, t3.x, acc[0][6]); acc[1][6] = fma2(a1, t3.x, acc[1][6]);
            acc[0][7] = fma2(a0, t3.y, acc[0][7]); acc[1][7] = fma2(a1, t3.y, acc[1][7]);
        }
    }

    // ---- epilogue: bias, LN(64) via shared atomics, gelu ----
    __syncthreads();
    if (tid < 128) { s_sum[tid] = 0.f; s_ssum[tid] = 0.f; }
    __syncthreads();
    float vals[4][8];
#pragma unroll
    for (int n = 0; n < 8; n++) {
        float bv = bias[tn * 8 + n];
        float2 p0 = unpack2(acc[0][n]);
        float2 p1 = unpack2(acc[1][n]);
        vals[0][n] = p0.x + bv; vals[1][n] = p0.y + bv;
        vals[2][n] = p1.x + bv; vals[3][n] = p1.y + bv;
    }
    int rows[4] = {2 * tm, 2 * tm + 1, 2 * tm + 64, 2 * tm + 65};
#pragma unroll
    for (int i = 0; i < 4; i++) {
        float s = 0.f, ss = 0.f;
#pragma unroll
        for (int n = 0; n < 8; n++) { s += vals[i][n]; ss += vals[i][n] * vals[i][n]; }
        atomicAdd(&s_sum[rows[i]], s);
        atomicAdd(&s_ssum[rows[i]], ss);
    }
    __syncthreads();
    if (tid < 128) {
        float mean = s_sum[tid] * (1.f / 64.f);
        float var  = s_ssum[tid] * (1.f / 64.f) - mean * mean;
        s_sum[tid] = mean;
        s_ssum[tid] = rsqrtf(var + 1e-5f);
    }
    __syncthreads();
#pragma unroll
    for (int i = 0; i < 4; i++) {
        float mean = s_sum[rows[i]], rstd = s_ssum[rows[i]];
        float o[8];
#pragma unroll
        for (int n = 0; n < 8; n++)
            o[n] = gelu_f((vals[i][n] - mean) * rstd * lng[tn * 8 + n] + lnb[tn * 8 + n]);
        float* dst = &g_h1[(m0 + rows[i]) * 64 + tn * 8];
        *reinterpret_cast<float4*>(dst)     = make_float4(o[0], o[1], o[2], o[3]);
        *reinterpret_cast<float4*>(dst + 4) = make_float4(o[4], o[5], o[6], o[7]);
    }
}

// =======================================================================
// conv2 implicit GEMM (f32x2): M=16384, N=256, K=1024. grid (128, 4).
// =======================================================================
__global__ __launch_bounds__(256) void conv2_kernel(const float* __restrict__ bias)
{
    __shared__ float As[32][132];
    __shared__ float Bs[32][132];
    const int tid = threadIdx.x;
    const int tm = tid & 31;
    const int tn = tid >> 5;
    const int ml = tid >> 1;
    const int q  = tid & 1;
    const int brow = tid >> 3;
    const int bq   = tid & 7;
    const int m0 = blockIdx.x * 128;
    const int n0 = blockIdx.y * 64;
    const int mg = m0 + ml;
    const int bt = mg >> 4, oh = (mg >> 2) & 3, ow = mg & 3;
    const float4* h4 = reinterpret_cast<const float4*>(g_h1);
    const float4* w4 = reinterpret_cast<const float4*>(g_w2t);

    u64 acc[2][8];
#pragma unroll
    for (int i = 0; i < 2; i++)
#pragma unroll
        for (int n = 0; n < 8; n++) acc[i][n] = 0ull;

    float4 ra[4], rb[2];
    {
        int ab = (bt * 256 + (oh * 4 + 0) * 16 + ow * 4 + 0) * 16 + 0 * 8 + q * 4;
#pragma unroll
        for (int v = 0; v < 4; v++) ra[v] = h4[ab + v];
        int bb = (0 * 32 + brow) * 64 + (n0 >> 2) + bq * 2;
        rb[0] = w4[bb]; rb[1] = w4[bb + 1];
    }
#pragma unroll 1
    for (int c = 0; c < 32; c++) {
        __syncthreads();
#pragma unroll
        for (int v = 0; v < 4; v++) {
            int k = q * 16 + v * 4;
            As[k + 0][ml] = ra[v].x; As[k + 1][ml] = ra[v].y;
            As[k + 2][ml] = ra[v].z; As[k + 3][ml] = ra[v].w;
        }
#pragma unroll
        for (int v = 0; v < 2; v++) {
            int nn = bq * 8 + v * 4;
            *reinterpret_cast<float4*>(&Bs[brow][nn * 2])     = make_float4(rb[v].x, rb[v].x, rb[v].y, rb[v].y);
            *reinterpret_cast<float4*>(&Bs[brow][nn * 2 + 4]) = make_float4(rb[v].z, rb[v].z, rb[v].w, rb[v].w);
        }
        __syncthreads();
        if (c + 1 < 32) {
            int cn = c + 1;
            int dy = cn >> 3, dx = (cn >> 1) & 3, cih = cn & 1;
            int ab = (bt * 256 + (oh * 4 + dy) * 16 + ow * 4 + dx) * 16 + cih * 8 + q * 4;
#pragma unroll
            for (int v = 0; v < 4; v++) ra[v] = h4[ab + v];
            int bb = (cn * 32 + brow) * 64 + (n0 >> 2) + bq * 2;
            rb[0] = w4[bb]; rb[1] = w4[bb + 1];
        }
#pragma unroll
        for (int kk = 0; kk < 32; kk++) {
            u64 a0 = *reinterpret_cast<const u64*>(&As[kk][2 * tm]);
            u64 a1 = *reinterpret_cast<const u64*>(&As[kk][2 * tm + 64]);
            ulonglong2 t0 = *reinterpret_cast<const ulonglong2*>(&Bs[kk][tn * 16 + 0]);
            ulonglong2 t1 = *reinterpret_cast<const ulonglong2*>(&Bs[kk][tn * 16 + 4]);
            ulonglong2 t2 = *reinterpret_cast<const ulonglong2*>(&Bs[kk][tn * 16 + 8]);
            ulonglong2 t3 = *reinterpret_cast<const ulonglong2*>(&Bs[kk][tn * 16 + 12]);
            acc[0][0] = fma2(a0, t0.x, acc[0][0]); acc[1][0] = fma2(a1, t0.x, acc[1][0]);
            acc[0][1] = fma2(a0, t0.y, acc[0][1]); acc[1][1] = fma2(a1, t0.y, acc[1][1]);
            acc[0][2] = fma2(a0, t1.x, acc[0][2]); acc[1][2] = fma2(a1, t1.x, acc[1][2]);
            acc[0][3] = fma2(a0, t1.y, acc[0][3]); acc[1][3] = fma2(a1, t1.y, acc[1][3]);
            acc[0][4] = fma2(a0, t2.x, acc[0][4]); acc[1][4] = fma2(a1, t2.x, acc[1][4]);
            acc[0][5] = fma2(a0, t2.y, acc[0][5]); acc[1][5] = fma2(a1, t2.y, acc[1][5]);
            acc[0][6] = fma2(a0, t3.x, acc[0][6]); acc[1][6] = fma2(a1, t3.x, acc[1][6]);
            acc[0][7] = fma2(a0, t3.y, acc[0][7]); acc[1][7] = fma2(a1, t3.y, acc[1][7]);
        }
    }
    int rows[4] = {2 * tm, 2 * tm + 1, 2 * tm + 64, 2 * tm + 65};
    float vals[4][8];
#pragma unroll
    for (int n = 0; n < 8; n++) {
        float bv = bias[n0 + tn * 8 + n];
        float2 p0 = unpack2(acc[0][n]);
        float2 p1 = unpack2(acc[1][n]);
        vals[0][n] = p0.x + bv; vals[1][n] = p0.y + bv;
        vals[2][n] = p1.x + bv; vals[3][n] = p1.y + bv;
    }
#pragma unroll
    for (int i = 0; i < 4; i++) {
        float* dst = &g_c2[(m0 + rows[i]) * 256 + n0 + tn * 8];
        *reinterpret_cast<float4*>(dst)     = make_float4(vals[i][0], vals[i][1], vals[i][2], vals[i][3]);
        *reinterpret_cast<float4*>(dst + 4) = make_float4(vals[i][4], vals[i][5], vals[i][6], vals[i][7]);
    }
}

// ---------------- LN(256) + gelu, in place on g_c2 ----------------
__global__ __launch_bounds__(256) void ln2_kernel(const float* __restrict__ lng, const float* __restrict__ lnb)
{
    int row = blockIdx.x, tid = threadIdx.x;
    float v = g_c2[row * 256 + tid];
    float a = v, qq = v * v;
#pragma unroll
    for (int o = 16; o > 0; o >>= 1) {
        a  += __shfl_down_sync(0xffffffffu, a,  o);
        qq += __shfl_down_sync(0xffffffffu, qq, o);
    }
    __shared__ float s1[8], s2[8];
    __shared__ float sm, sr;
    if ((tid & 31) == 0) { s1[tid >> 5] = a; s2[tid >> 5] = qq; }
    __syncthreads();
    if (tid == 0) {
        float A = 0.f, Q = 0.f;
#pragma unroll
        for (int i = 0; i < 8; i++) { A += s1[i]; Q += s2[i]; }
        float mean = A * (1.f / 256.f);
        float var  = Q * (1.f / 256.f) - mean * mean;
        sm = mean; sr = rsqrtf(var + 1e-5f);
    }
    __syncthreads();
    float xo = (v - sm) * sr * lng[tid] + lnb[tid];
    g_c2[row * 256 + tid] = gelu_f(xo);
}

// =======================================================================
// FC (f32x2): M=1024, N=512, K=4096. 64x64 tiles, grid (16, 8).
// per-thread 2 m-pairs x 4 n.
// =======================================================================
__global__ __launch_bounds__(256) void fc_kernel(const float* __restrict__ fcw, const float* __restrict__ fcb)
{
    __shared__ float As[32][68];
    __shared__ float Bs[32][132];
    const int tid = threadIdx.x;
    const int tm = tid & 15;            // m pairs at 2tm, 2tm+32
    const int tn = tid >> 4;            // n cols tn*4 .. +3  (0..15)
    const int ml = tid >> 2;            // A loader row (0..63)
    const int q  = tid & 3;             // A loader octet of 32 k
    const int brow = tid >> 3;          // B loader k row
    const int bq   = tid & 7;
    const int m0 = blockIdx.x * 64;
    const int n0 = blockIdx.y * 64;
    const float4* a4 = reinterpret_cast<const float4*>(g_c2);
    const float4* w4 = reinterpret_cast<const float4*>(fcw);

    u64 acc[2][4];
#pragma unroll
    for (int i = 0; i < 2; i++)
#pragma unroll
        for (int n = 0; n < 4; n++) acc[i][n] = 0ull;

    float4 ra[2], rb[2];
    {
        int ab = (m0 + ml) * 1024 + 0 * 8 + q * 2;
        ra[0] = a4[ab]; ra[1] = a4[ab + 1];
        int bb = (0 * 32 + brow) * 128 + (n0 >> 2) + bq * 2;
        rb[0] = w4[bb]; rb[1] = w4[bb + 1];
    }
#pragma unroll 1
    for (int c = 0; c < 128; c++) {
        __syncthreads();
        {
            int k = q * 8;
            As[k + 0][ml] = ra[0].x; As[k + 1][ml] = ra[0].y;
            As[k + 2][ml] = ra[0].z; As[k + 3][ml] = ra[0].w;
            As[k + 4][ml] = ra[1].x; As[k + 5][ml] = ra[1].y;
            As[k + 6][ml] = ra[1].z; As[k + 7][ml] = ra[1].w;
        }
#pragma unroll
        for (int v = 0; v < 2; v++) {
            int nn = bq * 8 + v * 4;
            *reinterpret_cast<float4*>(&Bs[brow][nn * 2])     = make_float4(rb[v].x, rb[v].x, rb[v].y, rb[v].y);
            *reinterpret_cast<float4*>(&Bs[brow][nn * 2 + 4]) = make_float4(rb[v].z, rb[v].z, rb[v].w, rb[v].w);
        }
        __syncthreads();
        if (c + 1 < 128) {
            int cn = c + 1;
            int ab = (m0 + ml) * 1024 + cn * 8 + q * 2;
            ra[0] = a4[ab]; ra[1] = a4[ab + 1];
            int bb = (cn * 32 + brow) * 128 + (n0 >> 2) + bq * 2;
            rb[0] = w4[bb]; rb[1] = w4[bb + 1];
        }
#pragma unroll
        for (int kk = 0; kk < 32; kk++) {
            u64 a0 = *reinterpret_cast<const u64*>(&As[kk][2 * tm]);
            u64 a1 = *reinterpret_cast<const u64*>(&As[kk][2 * tm + 32]);
            ulonglong2 t0 = *reinterpret_cast<const ulonglong2*>(&Bs[kk][tn * 8 + 0]);
            ulonglong2 t1 = *reinterpret_cast<const ulonglong2*>(&Bs[kk][tn * 8 + 4]);
            acc[0][0] = fma2(a0, t0.x, acc[0][0]); acc[1][0] = fma2(a1, t0.x, acc[1][0]);
            acc[0][1] = fma2(a0, t0.y, acc[0][1]); acc[1][1] = fma2(a1, t0.y, acc[1][1]);
            acc[0][2] = fma2(a0, t1.x, acc[0][2]); acc[1][2] = fma2(a1, t1.x, acc[1][2]);
            acc[0][3] = fma2(a0, t1.y, acc[0][3]); acc[1][3] = fma2(a1, t1.y, acc[1][3]);
        }
    }
    int rows[4] = {2 * tm, 2 * tm + 1, 2 * tm + 32, 2 * tm + 33};
    float vals[4][4];
#pragma unroll
    for (int n = 0; n < 4; n++) {
        float bv = fcb[n0 + tn * 4 + n];
        float2 p0 = unpack2(acc[0][n]);
        float2 p1 = unpack2(acc[1][n]);
        vals[0][n] = p0.x + bv; vals[1][n] = p0.y + bv;
        vals[2][n] = p1.x + bv; vals[3][n] = p1.y + bv;
    }
#pragma unroll
    for (int i = 0; i < 4; i++) {
        float* dst = &g_emb[(m0 + rows[i]) * 512 + n0 + tn * 4];
        *reinterpret_cast<float4*>(dst) = make_float4(vals[i][0], vals[i][1], vals[i][2], vals[i][3]);
    }
}

// =======================================================================
// Fourier top-2 gating. One block per batch, 512 threads (one per d).
// =======================================================================
__global__ __launch_bounds__(512) void gate_kernel(const float* __restrict__ wg)
{
    int b = blockIdx.x, tid = threadIdx.x;
    float v[16];
#pragma unroll
    for (int t = 0; t < 16; t++) v[t] = g_emb[(b * 16 + t) * 512 + tid];
    float amp[8];
#pragma unroll
    for (int f = 1; f <= 8; f++) {
        float re = 0.f, im = 0.f;
#pragma unroll
        for (int t = 0; t < 16; t++) {
            float ang = (float)(f * t) * 0.125f;   // angle/pi
            re += v[t] * cospif(ang);
            im -= v[t] * sinpif(ang);
        }
        amp[f - 1] = 0.25f * sqrtf(re * re + im * im);
    }
    __shared__ float red[512];
    __shared__ float asum[8];
    for (int j = 0; j < 8; j++) {
        red[tid] = amp[j];
        __syncthreads();
        for (int s = 256; s > 0; s >>= 1) {
            if (tid < s) red[tid] += red[tid + s];
            __syncthreads();
        }
        if (tid == 0) asum[j] = red[0];
        __syncthreads();
    }
    if (tid == 0) {
        float w[6];
        for (int e = 0; e < 6; e++) {
            float acc = 0.f;
            for (int f = 0; f < 8; f++) acc += asum[f] * (1.f / 512.f) * wg[f * 6 + e];
            w[e] = acc;
        }
        int i1 = 0;
        for (int e = 1; e < 6; e++) if (w[e] > w[i1]) i1 = e;
        int i2 = (i1 == 0) ? 1 : 0;
        for (int e = 0; e < 6; e++) if (e != i1 && w[e] > w[i2]) i2 = e;
        float e2 = expf(w[i2] - w[i1]);
        float s = 1.f + e2;
        for (int e = 0; e < 6; e++) g_gates[b * 6 + e] = 0.f;
        g_gates[b * 6 + i1] = 1.f / s;
        g_gates[b * 6 + i2] = e2 / s;
    }
}

// =======================================================================
// Experts: per (b, 128-col tile) block; <=2 gated experts; exp/sum/log fused.
// =======================================================================
__global__ __launch_bounds__(256) void expert_kernel(
    const float* __restrict__ ew, const float* __restrict__ eb, float* __restrict__ out)
{
    __shared__ float As[16 * 68];
    __shared__ float Bs[64 * 132];
    const int b  = blockIdx.x;
    const int n0 = blockIdx.y * 128;
    const int tid = threadIdx.x;
    const int tn  = tid & 63;
    const int tmg = tid >> 6;
    const int arow = tid >> 4, ap = tid & 15;
    const int brow = tid >> 2, bq = tid & 3;
    const float4* e4 = reinterpret_cast<const float4*>(g_emb);
    const float4* w4 = reinterpret_cast<const float4*>(ew);

    float comb[4][2] = {{0.f,0.f},{0.f,0.f},{0.f,0.f},{0.f,0.f}};

    for (int e = 0; e < 6; e++) {
        float g = g_gates[b * 6 + e];
        if (g == 0.f) continue;
        float acc[4][2] = {{0.f,0.f},{0.f,0.f},{0.f,0.f},{0.f,0.f}};
        float4 ra; float4 rb[8];
        {
            ra = e4[(b * 16 + arow) * 128 + 0 * 16 + ap];
            int bb = (e * 512 + 0 * 64 + brow) * 128 + (n0 >> 2);
#pragma unroll
            for (int it = 0; it < 8; it++) rb[it] = w4[bb + bq + 4 * it];
        }
        for (int c = 0; c < 8; c++) {
            __syncthreads();
            *reinterpret_cast<float4*>(&As[arow * 68 + ap * 4]) = ra;
#pragma unroll
            for (int it = 0; it < 8; it++)
                *reinterpret_cast<float4*>(&Bs[brow * 132 + (bq + 4 * it) * 4]) = rb[it];
            __syncthreads();
            if (c + 1 < 8) {
                ra = e4[(b * 16 + arow) * 128 + (c + 1) * 16 + ap];
                int bb = (e * 512 + (c + 1) * 64 + brow) * 128 + (n0 >> 2);
#pragma unroll
                for (int it = 0; it < 8; it++) rb[it] = w4[bb + bq + 4 * it];
            }
#pragma unroll 16
            for (int kk = 0; kk < 64; kk++) {
                float2 bv = *reinterpret_cast<const float2*>(&Bs[kk * 132 + tn * 2]);
                float a0 = As[(tmg * 4 + 0) * 68 + kk];
                float a1 = As[(tmg * 4 + 1) * 68 + kk];
                float a2 = As[(tmg * 4 + 2) * 68 + kk];
                float a3 = As[(tmg * 4 + 3) * 68 + kk];
                acc[0][0] += a0 * bv.x; acc[0][1] += a0 * bv.y;
                acc[1][0] += a1 * bv.x; acc[1][1] += a1 * bv.y;
                acc[2][0] += a2 * bv.x; acc[2][1] += a2 * bv.y;
                acc[3][0] += a3 * bv.x; acc[3][1] += a3 * bv.y;
            }
        }
        float bb0 = eb[e * 512 + n0 + tn * 2 + 0];
        float bb1 = eb[e * 512 + n0 + tn * 2 + 1];
#pragma unroll
        for (int i = 0; i < 4; i++) {
            comb[i][0] += g * expf(acc[i][0] + bb0);
            comb[i][1] += g * expf(acc[i][1] + bb1);
        }
    }
#pragma unroll
    for (int i = 0; i < 4; i++) {
        int m = tmg * 4 + i;
        float c0 = comb[i][0]; if (c0 == 0.f) c0 = 2.2204460492503131e-16f;
        float c1 = comb[i][1]; if (c1 == 0.f) c1 = 2.2204460492503131e-16f;
        float2 o = make_float2(logf(c0), logf(c1));
        *reinterpret_cast<float2*>(&out[(b * 16 + m) * 512 + n0 + tn * 2]) = o;
    }
}

// ---------------- launcher ----------------
extern "C" void kernel_launch(void* const* d_in, const int* in_sizes, int n_in,
                              void* d_out, int out_size)
{
    (void)in_sizes; (void)n_in; (void)out_size;
    const float* x   = (const float*)d_in[0];
    const float* w1  = (const float*)d_in[1];
    const float* b1  = (const float*)d_in[2];
    const float* g1  = (const float*)d_in[3];
    const float* be1 = (const float*)d_in[4];
    const float* w2  = (const float*)d_in[5];
    const float* b2  = (const float*)d_in[6];
    const float* g2  = (const float*)d_in[7];
    const float* be2 = (const float*)d_in[8];
    const float* fcw = (const float*)d_in[9];
    const float* fcb = (const float*)d_in[10];
    const float* wg  = (const float*)d_in[11];
    const float* ew  = (const float*)d_in[12];
    const float* eb  = (const float*)d_in[13];
    float* out = (float*)d_out;

    prep_weights<<<1024, 256>>>(w1, w2);
    conv1_kernel<<<2048, 256>>>(x, b1, g1, be1);
    conv2_kernel<<<dim3(128, 4), 256>>>(b2);
    ln2_kernel<<<16384, 256>>>(g2, be2);
    fc_kernel<<<dim3(16, 8), 256>>>(fcw, fcb);
    gate_kernel<<<64, 512>>>(wg);
    expert_kernel<<<dim3(64, 4), 256>>>(ew, eb, out);
}

// round 13
// speedup vs baseline: 1.0472x; 1.0472x over previous
#include <cuda_runtime.h>
#include <cuda_bf16.h>
#include <math.h>

// ---------------- static scratch (no allocations allowed) ----------------
// sizes: B=64 T=16 H=W=64 C=16 -> BT=1024
__device__ float g_w1t[256 * 64];          // conv1 weights, k-major  (k = dy*64+dx*16+ci)
__device__ float g_w2t[1024 * 256];        // conv2 weights, k-major  (k = dy*256+dx*64+ci)
__device__ float g_h1[1024 * 256 * 64];    // conv1 out, (bt,oh,ow,64) channels-last, post LN+gelu
__device__ float g_c2[16384 * 256];        // conv2 out rows; LN+gelu applied in place
__device__ float g_emb[1024 * 512];        // fc out (bt, 512)
__device__ float g_gates[64 * 6];          // gate weights per batch

typedef unsigned long long u64;

__device__ __forceinline__ float gelu_f(float v) {
    return 0.5f * v * (1.0f + erff(v * 0.70710678118654752440f));
}

__device__ __forceinline__ u64 fma2(u64 a, u64 b, u64 c) {
    asm("fma.rn.f32x2 %0, %1, %2, %0;" : "+l"(c) : "l"(a), "l"(b));
    return c;
}
__device__ __forceinline__ float2 unpack2(u64 v) {
    float2 r;
    asm("mov.b64 {%0, %1}, %2;" : "=f"(r.x), "=f"(r.y) : "l"(v));
    return r;
}

// ---------------- weight re-layout (k-major for GEMM B tiles) ----------------
__global__ void prep_weights(const float* __restrict__ w1, const float* __restrict__ w2) {
    int i = blockIdx.x * 256 + threadIdx.x;
    if (i < 16384) {                 // w1: (co,ci,dy,dx) -> w1t[k*64+co], k=(dy,dx,ci)
        int k = i >> 6, co = i & 63;
        int dy = k >> 6, dx = (k >> 4) & 3, ci = k & 15;
        g_w1t[i] = w1[((co * 16 + ci) * 4 + dy) * 4 + dx];
    }
    if (i < 262144) {                // w2: (co,ci,dy,dx) -> w2t[k*256+co], k=(dy,dx,ci)
        int k = i >> 8, co = i & 255;
        int dy = k >> 8, dx = (k >> 6) & 3, ci = k & 63;
        g_w2t[i] = w2[((co * 64 + ci) * 4 + dy) * 4 + dx];
    }
}

// =======================================================================
// conv1 implicit GEMM with packed f32x2: M=262144, N=64, K=256
// block 128m x 64n, 256 thr, per-thread 2 m-pairs x 8 n.
// As[k][m] transposed (m-pairs contiguous); Bs duplicated pairs.
// epilogue: bias + LN(64) + gelu fused.
// =======================================================================
__global__ __launch_bounds__(256) void conv1_kernel(
    const float* __restrict__ x, const float* __restrict__ bias,
    const float* __restrict__ lng, const float* __restrict__ lnb)
{
    __shared__ float As[32][132];
    __shared__ float Bs[32][132];
    __shared__ float s_sum[128];
    __shared__ float s_ssum[128];
    const int tid = threadIdx.x;
    const int tm = tid & 31;            // m pair groups: pairs at 2tm, 2tm+64
    const int tn = tid >> 5;            // n cols tn*8 .. +7
    const int ml = tid >> 1;            // A loader row (0..127)
    const int q  = tid & 1;             // A loader half of 32 k
    const int brow = tid >> 3;          // B loader k row (0..31)
    const int bq   = tid & 7;           // B loader n-octet
    const int m0 = blockIdx.x * 128;
    const int mg = m0 + ml;
    const int bt = mg >> 8, oh = (mg >> 4) & 15, ow = mg & 15;
    const float4* x4 = reinterpret_cast<const float4*>(x);
    const float4* w4 = reinterpret_cast<const float4*>(g_w1t);

    u64 acc[2][8];
#pragma unroll
    for (int i = 0; i < 2; i++)
#pragma unroll
        for (int n = 0; n < 8; n++) acc[i][n] = 0ull;

    float4 ra[4], rb[2];
    {   // prefetch chunk 0 (dy=0, dx-half=0)
        int ab = ((bt * 64 + oh * 4 + 0) * 64 + ow * 4 + 0) * 4 + q * 4;
#pragma unroll
        for (int v = 0; v < 4; v++) ra[v] = x4[ab + v];
        int bb = (0 * 32 + brow) * 16 + bq * 2;
        rb[0] = w4[bb]; rb[1] = w4[bb + 1];
    }
#pragma unroll 1
    for (int c = 0; c < 8; c++) {
        __syncthreads();
#pragma unroll
        for (int v = 0; v < 4; v++) {        // A transposed scalar stores
            int k = q * 16 + v * 4;
            As[k + 0][ml] = ra[v].x; As[k + 1][ml] = ra[v].y;
            As[k + 2][ml] = ra[v].z; As[k + 3][ml] = ra[v].w;
        }
#pragma unroll
        for (int v = 0; v < 2; v++) {        // B duplicated-pair stores
            int nn = bq * 8 + v * 4;
            *reinterpret_cast<float4*>(&Bs[brow][nn * 2])     = make_float4(rb[v].x, rb[v].x, rb[v].y, rb[v].y);
            *reinterpret_cast<float4*>(&Bs[brow][nn * 2 + 4]) = make_float4(rb[v].z, rb[v].z, rb[v].w, rb[v].w);
        }
        __syncthreads();
        if (c + 1 < 8) {
            int cn = c + 1, dy = cn >> 1, dxh = cn & 1;
            int ab = ((bt * 64 + oh * 4 + dy) * 64 + ow * 4 + dxh * 2) * 4 + q * 4;
#pragma unroll
            for (int v = 0; v < 4; v++) ra[v] = x4[ab + v];
            int bb = (cn * 32 + brow) * 16 + bq * 2;
            rb[0] = w4[bb]; rb[1] = w4[bb + 1];
        }
#pragma unroll
        for (int kk = 0; kk < 32; kk++) {
            u64 a0 = *reinterpret_cast<const u64*>(&As[kk][2 * tm]);
            u64 a1 = *reinterpret_cast<const u64*>(&As[kk][2 * tm + 64]);
            ulonglong2 t0 = *reinterpret_cast<const ulonglong2*>(&Bs[kk][tn * 16 + 0]);
            ulonglong2 t1 = *reinterpret_cast<const ulonglong2*>(&Bs[kk][tn * 16 + 4]);
            ulonglong2 t2 = *reinterpret_cast<const ulonglong2*>(&Bs[kk][tn * 16 + 8]);
            ulonglong2 t3 = *reinterpret_cast<const ulonglong2*>(&Bs[kk][tn * 16 + 12]);
            acc[0][0] = fma2(a0, t0.x, acc[0][0]); acc[1][0] = fma2(a1, t0.x, acc[1][0]);
            acc[0][1] = fma2(a0, t0.y, acc[0][1]); acc[1][1] = fma2(a1, t0.y, acc[1][1]);
            acc[0][2] = fma2(a0, t1.x, acc[0][2]); acc[1][2] = fma2(a1, t1.x, acc[1][2]);
            acc[0][3] = fma2(a0, t1.y, acc[0][3]); acc[1][3] = fma2(a1, t1.y, acc[1][3]);
            acc[0][4] = fma2(a0, t2.x, acc[0][4]); acc[1][4] = fma2(a1, t2.x, acc[1][4]);
            acc[0][5] = fma2(a0, t2.y, acc[0][5]); acc[1][5] = fma2(a1, t2.y, acc[1][5]);
            acc[0][6] = fma2(a0, t3.x, acc[0][6]); acc[1][6] = fma2(a1, t3.x, acc[1][6]);
            acc[0][7] = fma2(a0, t3.y, acc[0][7]); acc[1][7] = fma2(a1, t3.y, acc[1][7]);
        }
    }

    // ---- epilogue: bias, LN(64) via shared atomics, gelu ----
    __syncthreads();
    if (tid < 128) { s_sum[tid] = 0.f; s_ssum[tid] = 0.f; }
    __syncthreads();
    float vals[4][8];
#pragma unroll
    for (int n = 0; n < 8; n++) {
        float bv = bias[tn * 8 + n];
        float2 p0 = unpack2(acc[0][n]);
        float2 p1 = unpack2(acc[1][n]);
        vals[0][n] = p0.x + bv; vals[1][n] = p0.y + bv;
        vals[2][n] = p1.x + bv; vals[3][n] = p1.y + bv;
    }
    int rows[4] = {2 * tm, 2 * tm + 1, 2 * tm + 64, 2 * tm + 65};
#pragma unroll
    for (int i = 0; i < 4; i++) {
        float s = 0.f, ss = 0.f;
#pragma unroll
        for (int n = 0; n < 8; n++) { s += vals[i][n]; ss += vals[i][n] * vals[i][n]; }
        atomicAdd(&s_sum[rows[i]], s);
        atomicAdd(&s_ssum[rows[i]], ss);
    }
    __syncthreads();
    if (tid < 128) {
        float mean = s_sum[tid] * (1.f / 64.f);
        float var  = s_ssum[tid] * (1.f / 64.f) - mean * mean;
        s_sum[tid] = mean;
        s_ssum[tid] = rsqrtf(var + 1e-5f);
    }
    __syncthreads();
#pragma unroll
    for (int i = 0; i < 4; i++) {
        float mean = s_sum[rows[i]], rstd = s_ssum[rows[i]];
        float o[8];
#pragma unroll
        for (int n = 0; n < 8; n++)
            o[n] = gelu_f((vals[i][n] - mean) * rstd * lng[tn * 8 + n] + lnb[tn * 8 + n]);
        float* dst = &g_h1[(m0 + rows[i]) * 64 + tn * 8];
        *reinterpret_cast<float4*>(dst)     = make_float4(o[0], o[1], o[2], o[3]);
        *reinterpret_cast<float4*>(dst + 4) = make_float4(o[4], o[5], o[6], o[7]);
    }
}

// =======================================================================
// conv2 implicit GEMM (f32x2): M=16384, N=256, K=1024. grid (128, 4).
// =======================================================================
__global__ __launch_bounds__(256) void conv2_kernel(const float* __restrict__ bias)
{
    __shared__ float As[32][132];
    __shared__ float Bs[32][132];
    const int tid = threadIdx.x;
    const int tm = tid & 31;
    const int tn = tid >> 5;
    const int ml = tid >> 1;
    const int q  = tid & 1;
    const int brow = tid >> 3;
    const int bq   = tid & 7;
    const int m0 = blockIdx.x * 128;
    const int n0 = blockIdx.y * 64;
    const int mg = m0 + ml;
    const int bt = mg >> 4, oh = (mg >> 2) & 3, ow = mg & 3;
    const float4* h4 = reinterpret_cast<const float4*>(g_h1);
    const float4* w4 = reinterpret_cast<const float4*>(g_w2t);

    u64 acc[2][8];
#pragma unroll
    for (int i = 0; i < 2; i++)
#pragma unroll
        for (int n = 0; n < 8; n++) acc[i][n] = 0ull;

    float4 ra[4], rb[2];
    {
        int ab = (bt * 256 + (oh * 4 + 0) * 16 + ow * 4 + 0) * 16 + 0 * 8 + q * 4;
#pragma unroll
        for (int v = 0; v < 4; v++) ra[v] = h4[ab + v];
        int bb = (0 * 32 + brow) * 64 + (n0 >> 2) + bq * 2;
        rb[0] = w4[bb]; rb[1] = w4[bb + 1];
    }
#pragma unroll 1
    for (int c = 0; c < 32; c++) {
        __syncthreads();
#pragma unroll
        for (int v = 0; v < 4; v++) {
            int k = q * 16 + v * 4;
            As[k + 0][ml] = ra[v].x; As[k + 1][ml] = ra[v].y;
            As[k + 2][ml] = ra[v].z; As[k + 3][ml] = ra[v].w;
        }
#pragma unroll
        for (int v = 0; v < 2; v++) {
            int nn = bq * 8 + v * 4;
            *reinterpret_cast<float4*>(&Bs[brow][nn * 2])     = make_float4(rb[v].x, rb[v].x, rb[v].y, rb[v].y);
            *reinterpret_cast<float4*>(&Bs[brow][nn * 2 + 4]) = make_float4(rb[v].z, rb[v].z, rb[v].w, rb[v].w);
        }
        __syncthreads();
        if (c + 1 < 32) {
            int cn = c + 1;
            int dy = cn >> 3, dx = (cn >> 1) & 3, cih = cn & 1;
            int ab = (bt * 256 + (oh * 4 + dy) * 16 + ow * 4 + dx) * 16 + cih * 8 + q * 4;
#pragma unroll
            for (int v = 0; v < 4; v++) ra[v] = h4[ab + v];
            int bb = (cn * 32 + brow) * 64 + (n0 >> 2) + bq * 2;
            rb[0] = w4[bb]; rb[1] = w4[bb + 1];
        }
#pragma unroll
        for (int kk = 0; kk < 32; kk++) {
            u64 a0 = *reinterpret_cast<const u64*>(&As[kk][2 * tm]);
            u64 a1 = *reinterpret_cast<const u64*>(&As[kk][2 * tm + 64]);
            ulonglong2 t0 = *reinterpret_cast<const ulonglong2*>(&Bs[kk][tn * 16 + 0]);
            ulonglong2 t1 = *reinterpret_cast<const ulonglong2*>(&Bs[kk][tn * 16 + 4]);
            ulonglong2 t2 = *reinterpret_cast<const ulonglong2*>(&Bs[kk][tn * 16 + 8]);
            ulonglong2 t3 = *reinterpret_cast<const ulonglong2*>(&Bs[kk][tn * 16 + 12]);
            acc[0][0] = fma2(a0, t0.x, acc[0][0]); acc[1][0] = fma2(a1, t0.x, acc[1][0]);
            acc[0][1] = fma2(a0, t0.y, acc[0][1]); acc[1][1] = fma2(a1, t0.y, acc[1][1]);
            acc[0][2] = fma2(a0, t1.x, acc[0][2]); acc[1][2] = fma2(a1, t1.x, acc[1][2]);
            acc[0][3] = fma2(a0, t1.y, acc[0][3]); acc[1][3] = fma2(a1, t1.y, acc[1][3]);
            acc[0][4] = fma2(a0, t2.x, acc[0][4]); acc[1][4] = fma2(a1, t2.x, acc[1][4]);
            acc[0][5] = fma2(a0, t2.y, acc[0][5]); acc[1][5] = fma2(a1, t2.y, acc[1][5]);
            acc[0][6] = fma2(a0, t3.x, acc[0][6]); acc[1][6] = fma2(a1, t3.x, acc[1][6]);
            acc[0][7] = fma2(a0, t3.y, acc[0][7]); acc[1][7] = fma2(a1, t3.y, acc[1][7]);
        }
    }
    int rows[4] = {2 * tm, 2 * tm + 1, 2 * tm + 64, 2 * tm + 65};
    float vals[4][8];
#pragma unroll
    for (int n = 0; n < 8; n++) {
        float bv = bias[n0 + tn * 8 + n];
        float2 p0 = unpack2(acc[0][n]);
        float2 p1 = unpack2(acc[1][n]);
        vals[0][n] = p0.x + bv; vals[1][n] = p0.y + bv;
        vals[2][n] = p1.x + bv; vals[3][n] = p1.y + bv;
    }
#pragma unroll
    for (int i = 0; i < 4; i++) {
        float* dst = &g_c2[(m0 + rows[i]) * 256 + n0 + tn * 8];
        *reinterpret_cast<float4*>(dst)     = make_float4(vals[i][0], vals[i][1], vals[i][2], vals[i][3]);
        *reinterpret_cast<float4*>(dst + 4) = make_float4(vals[i][4], vals[i][5], vals[i][6], vals[i][7]);
    }
}

// ---------------- LN(256) + gelu, in place on g_c2 ----------------
__global__ __launch_bounds__(256) void ln2_kernel(const float* __restrict__ lng, const float* __restrict__ lnb)
{
    int row = blockIdx.x, tid = threadIdx.x;
    float v = g_c2[row * 256 + tid];
    float a = v, qq = v * v;
#pragma unroll
    for (int o = 16; o > 0; o >>= 1) {
        a  += __shfl_down_sync(0xffffffffu, a,  o);
        qq += __shfl_down_sync(0xffffffffu, qq, o);
    }
    __shared__ float s1[8], s2[8];
    __shared__ float sm, sr;
    if ((tid & 31) == 0) { s1[tid >> 5] = a; s2[tid >> 5] = qq; }
    __syncthreads();
    if (tid == 0) {
        float A = 0.f, Q = 0.f;
#pragma unroll
        for (int i = 0; i < 8; i++) { A += s1[i]; Q += s2[i]; }
        float mean = A * (1.f / 256.f);
        float var  = Q * (1.f / 256.f) - mean * mean;
        sm = mean; sr = rsqrtf(var + 1e-5f);
    }
    __syncthreads();
    float xo = (v - sm) * sr * lng[tid] + lnb[tid];
    g_c2[row * 256 + tid] = gelu_f(xo);
}

// =======================================================================
// FC (f32x2): M=1024, N=512, K=4096. 64x64 tiles, grid (16, 8).
// per-thread 2 m-pairs x 4 n.
// =======================================================================
__global__ __launch_bounds__(256) void fc_kernel(const float* __restrict__ fcw, const float* __restrict__ fcb)
{
    __shared__ float As[32][68];
    __shared__ float Bs[32][132];
    const int tid = threadIdx.x;
    const int tm = tid & 15;            // m pairs at 2tm, 2tm+32
    const int tn = tid >> 4;            // n cols tn*4 .. +3  (0..15)
    const int ml = tid >> 2;            // A loader row (0..63)
    const int q  = tid & 3;             // A loader octet of 32 k
    const int brow = tid >> 3;          // B loader k row
    const int bq   = tid & 7;
    const int m0 = blockIdx.x * 64;
    const int n0 = blockIdx.y * 64;
    const float4* a4 = reinterpret_cast<const float4*>(g_c2);
    const float4* w4 = reinterpret_cast<const float4*>(fcw);

    u64 acc[2][4];
#pragma unroll
    for (int i = 0; i < 2; i++)
#pragma unroll
        for (int n = 0; n < 4; n++) acc[i][n] = 0ull;

    float4 ra[2], rb[2];
    {
        int ab = (m0 + ml) * 1024 + 0 * 8 + q * 2;
        ra[0] = a4[ab]; ra[1] = a4[ab + 1];
        int bb = (0 * 32 + brow) * 128 + (n0 >> 2) + bq * 2;
        rb[0] = w4[bb]; rb[1] = w4[bb + 1];
    }
#pragma unroll 1
    for (int c = 0; c < 128; c++) {
        __syncthreads();
        {
            int k = q * 8;
            As[k + 0][ml] = ra[0].x; As[k + 1][ml] = ra[0].y;
            As[k + 2][ml] = ra[0].z; As[k + 3][ml] = ra[0].w;
            As[k + 4][ml] = ra[1].x; As[k + 5][ml] = ra[1].y;
            As[k + 6][ml] = ra[1].z; As[k + 7][ml] = ra[1].w;
        }
#pragma unroll
        for (int v = 0; v < 2; v++) {
            int nn = bq * 8 + v * 4;
            *reinterpret_cast<float4*>(&Bs[brow][nn * 2])     = make_float4(rb[v].x, rb[v].x, rb[v].y, rb[v].y);
            *reinterpret_cast<float4*>(&Bs[brow][nn * 2 + 4]) = make_float4(rb[v].z, rb[v].z, rb[v].w, rb[v].w);
        }
        __syncthreads();
        if (c + 1 < 128) {
            int cn = c + 1;
            int ab = (m0 + ml) * 1024 + cn * 8 + q * 2;
            ra[0] = a4[ab]; ra[1] = a4[ab + 1];
            int bb = (cn * 32 + brow) * 128 + (n0 >> 2) + bq * 2;
            rb[0] = w4[bb]; rb[1] = w4[bb + 1];
        }
#pragma unroll
        for (int kk = 0; kk < 32; kk++) {
            u64 a0 = *reinterpret_cast<const u64*>(&As[kk][2 * tm]);
            u64 a1 = *reinterpret_cast<const u64*>(&As[kk][2 * tm + 32]);
            ulonglong2 t0 = *reinterpret_cast<const ulonglong2*>(&Bs[kk][tn * 8 + 0]);
            ulonglong2 t1 = *reinterpret_cast<const ulonglong2*>(&Bs[kk][tn * 8 + 4]);
            acc[0][0] = fma2(a0, t0.x, acc[0][0]); acc[1][0] = fma2(a1, t0.x, acc[1][0]);
            acc[0][1] = fma2(a0, t0.y, acc[0][1]); acc[1][1] = fma2(a1, t0.y, acc[1][1]);
            acc[0][2] = fma2(a0, t1.x, acc[0][2]); acc[1][2] = fma2(a1, t1.x, acc[1][2]);
            acc[0][3] = fma2(a0, t1.y, acc[0][3]); acc[1][3] = fma2(a1, t1.y, acc[1][3]);
        }
    }
    int rows[4] = {2 * tm, 2 * tm + 1, 2 * tm + 32, 2 * tm + 33};
    float vals[4][4];
#pragma unroll
    for (int n = 0; n < 4; n++) {
        float bv = fcb[n0 + tn * 4 + n];
        float2 p0 = unpack2(acc[0][n]);
        float2 p1 = unpack2(acc[1][n]);
        vals[0][n] = p0.x + bv; vals[1][n] = p0.y + bv;
        vals[2][n] = p1.x + bv; vals[3][n] = p1.y + bv;
    }
#pragma unroll
    for (int i = 0; i < 4; i++) {
        float* dst = &g_emb[(m0 + rows[i]) * 512 + n0 + tn * 4];
        *reinterpret_cast<float4*>(dst) = make_float4(vals[i][0], vals[i][1], vals[i][2], vals[i][3]);
    }
}

// =======================================================================
// Fourier top-2 gating. One block per batch, 512 threads (one per d).
// =======================================================================
__global__ __launch_bounds__(512) void gate_kernel(const float* __restrict__ wg)
{
    int b = blockIdx.x, tid = threadIdx.x;
    float v[16];
#pragma unroll
    for (int t = 0; t < 16; t++) v[t] = g_emb[(b * 16 + t) * 512 + tid];
    float amp[8];
#pragma unroll
    for (int f = 1; f <= 8; f++) {
        float re = 0.f, im = 0.f;
#pragma unroll
        for (int t = 0; t < 16; t++) {
            float ang = (float)(f * t) * 0.125f;   // angle/pi
            re += v[t] * cospif(ang);
            im -= v[t] * sinpif(ang);
        }
        amp[f - 1] = 0.25f * sqrtf(re * re + im * im);
    }
    __shared__ float red[512];
    __shared__ float asum[8];
    for (int j = 0; j < 8; j++) {
        red[tid] = amp[j];
        __syncthreads();
        for (int s = 256; s > 0; s >>= 1) {
            if (tid < s) red[tid] += red[tid + s];
            __syncthreads();
        }
        if (tid == 0) asum[j] = red[0];
        __syncthreads();
    }
    if (tid == 0) {
        float w[6];
        for (int e = 0; e < 6; e++) {
            float acc = 0.f;
            for (int f = 0; f < 8; f++) acc += asum[f] * (1.f / 512.f) * wg[f * 6 + e];
            w[e] = acc;
        }
        int i1 = 0;
        for (int e = 1; e < 6; e++) if (w[e] > w[i1]) i1 = e;
        int i2 = (i1 == 0) ? 1 : 0;
        for (int e = 0; e < 6; e++) if (e != i1 && w[e] > w[i2]) i2 = e;
        float e2 = expf(w[i2] - w[i1]);
        float s = 1.f + e2;
        for (int e = 0; e < 6; e++) g_gates[b * 6 + e] = 0.f;
        g_gates[b * 6 + i1] = 1.f / s;
        g_gates[b * 6 + i2] = e2 / s;
    }
}

// =======================================================================
// Experts: per (b, 128-col tile) block; <=2 gated experts; exp/sum/log fused.
// =======================================================================
__global__ __launch_bounds__(256) void expert_kernel(
    const float* __restrict__ ew, const float* __restrict__ eb, float* __restrict__ out)
{
    __shared__ float As[16 * 68];
    __shared__ float Bs[64 * 132];
    const int b  = blockIdx.x;
    const int n0 = blockIdx.y * 128;
    const int tid = threadIdx.x;
    const int tn  = tid & 63;
    const int tmg = tid >> 6;
    const int arow = tid >> 4, ap = tid & 15;
    const int brow = tid >> 2, bq = tid & 3;
    const float4* e4 = reinterpret_cast<const float4*>(g_emb);
    const float4* w4 = reinterpret_cast<const float4*>(ew);

    float comb[4][2] = {{0.f,0.f},{0.f,0.f},{0.f,0.f},{0.f,0.f}};

    for (int e = 0; e < 6; e++) {
        float g = g_gates[b * 6 + e];
        if (g == 0.f) continue;
        float acc[4][2] = {{0.f,0.f},{0.f,0.f},{0.f,0.f},{0.f,0.f}};
        float4 ra; float4 rb[8];
        {
            ra = e4[(b * 16 + arow) * 128 + 0 * 16 + ap];
            int bb = (e * 512 + 0 * 64 + brow) * 128 + (n0 >> 2);
#pragma unroll
            for (int it = 0; it < 8; it++) rb[it] = w4[bb + bq + 4 * it];
        }
        for (int c = 0; c < 8; c++) {
            __syncthreads();
            *reinterpret_cast<float4*>(&As[arow * 68 + ap * 4]) = ra;
#pragma unroll
            for (int it = 0; it < 8; it++)
                *reinterpret_cast<float4*>(&Bs[brow * 132 + (bq + 4 * it) * 4]) = rb[it];
            __syncthreads();
            if (c + 1 < 8) {
                ra = e4[(b * 16 + arow) * 128 + (c + 1) * 16 + ap];
                int bb = (e * 512 + (c + 1) * 64 + brow) * 128 + (n0 >> 2);
#pragma unroll
                for (int it = 0; it < 8; it++) rb[it] = w4[bb + bq + 4 * it];
            }
#pragma unroll 16
            for (int kk = 0; kk < 64; kk++) {
                float2 bv = *reinterpret_cast<const float2*>(&Bs[kk * 132 + tn * 2]);
                float a0 = As[(tmg * 4 + 0) * 68 + kk];
                float a1 = As[(tmg * 4 + 1) * 68 + kk];
                float a2 = As[(tmg * 4 + 2) * 68 + kk];
                float a3 = As[(tmg * 4 + 3) * 68 + kk];
                acc[0][0] += a0 * bv.x; acc[0][1] += a0 * bv.y;
                acc[1][0] += a1 * bv.x; acc[1][1] += a1 * bv.y;
                acc[2][0] += a2 * bv.x; acc[2][1] += a2 * bv.y;
                acc[3][0] += a3 * bv.x; acc[3][1] += a3 * bv.y;
            }
        }
        float bb0 = eb[e * 512 + n0 + tn * 2 + 0];
        float bb1 = eb[e * 512 + n0 + tn * 2 + 1];
#pragma unroll
        for (int i = 0; i < 4; i++) {
            comb[i][0] += g * expf(acc[i][0] + bb0);
            comb[i][1] += g * expf(acc[i][1] + bb1);
        }
    }
#pragma unroll
    for (int i = 0; i < 4; i++) {
        int m = tmg * 4 + i;
        float c0 = comb[i][0]; if (c0 == 0.f) c0 = 2.2204460492503131e-16f;
        float c1 = comb[i][1]; if (c1 == 0.f) c1 = 2.2204460492503131e-16f;
        float2 o = make_float2(logf(c0), logf(c1));
        *reinterpret_cast<float2*>(&out[(b * 16 + m) * 512 + n0 + tn * 2]) = o;
    }
}

// ---------------- launcher ----------------
extern "C" void kernel_launch(void* const* d_in, const int* in_sizes, int n_in,
                              void* d_out, int out_size)
{
    (void)in_sizes; (void)n_in; (void)out_size;
    const float* x   = (const float*)d_in[0];
    const float* w1  = (const float*)d_in[1];
    const float* b1  = (const float*)d_in[2];
    const float* g1  = (const float*)d_in[3];
    const float* be1 = (const float*)d_in[4];
    const float* w2  = (const float*)d_in[5];
    const float* b2  = (const float*)d_in[6];
    const float* g2  = (const float*)d_in[7];
    const float* be2 = (const float*)d_in[8];
    const float* fcw = (const float*)d_in[9];
    const float* fcb = (const float*)d_in[10];
    const float* wg  = (const float*)d_in[11];
    const float* ew  = (const float*)d_in[12];
    const float* eb  = (const float*)d_in[13];
    float* out = (float*)d_out;

    prep_weights<<<1024, 256>>>(w1, w2);
    conv1_kernel<<<2048, 256>>>(x, b1, g1, be1);
    conv2_kernel<<<dim3(128, 4), 256>>>(b2);
    ln2_kernel<<<16384, 256>>>(g2, be2);
    fc_kernel<<<dim3(16, 8), 256>>>(fcw, fcb);
    gate_kernel<<<64, 512>>>(wg);
    expert_kernel<<<dim3(64, 4), 256>>>(ew, eb, out);
}

// round 17
// speedup vs baseline: 2.1054x; 2.0105x over previous
#include <cuda_runtime.h>
#include <cuda_bf16.h>
#include <math.h>
#include <stdint.h>

// ================= static scratch (no allocations allowed) =================
// B=64 T=16 H=W=64 C=16 -> BT=1024
__device__ __align__(16) __nv_bfloat16 g_w1h[64 * 256],   g_w1l[64 * 256];    // conv1 W, n-major [co][k]
__device__ __align__(16) __nv_bfloat16 g_w2h[256 * 1024], g_w2l[256 * 1024];  // conv2 W, n-major [co][k]
__device__ __align__(16) __nv_bfloat16 g_fwh[512 * 4096], g_fwl[512 * 4096];  // fc W,    n-major [n][k]
__device__ float g_h1[1024 * 256 * 64];    // conv1 out (pixel-major, 64ch), post LN+gelu
__device__ float g_c2[16384 * 256];        // conv2 out rows; LN+gelu in place
__device__ float g_emb[1024 * 512];        // fc out
__device__ float g_gates[64 * 6];

__device__ __forceinline__ float gelu_f(float v) {
    return 0.5f * v * (1.0f + erff(v * 0.70710678118654752440f));
}

__device__ __forceinline__ uint32_t smem_u32(const void* p) {
    uint32_t a;
    asm("{ .reg .u64 t; cvta.to.shared.u64 t, %1; cvt.u32.u64 %0, t; }" : "=r"(a) : "l"(p));
    return a;
}
__device__ __forceinline__ void ldm_x4(uint32_t* r, uint32_t addr) {
    asm volatile("ldmatrix.sync.aligned.m8n8.x4.shared.b16 {%0,%1,%2,%3}, [%4];"
                 : "=r"(r[0]), "=r"(r[1]), "=r"(r[2]), "=r"(r[3]) : "r"(addr));
}
__device__ __forceinline__ void mma_bf16(float* d, const uint32_t* a, const uint32_t* b) {
    asm volatile("mma.sync.aligned.m16n8k16.row.col.f32.bf16.bf16.f32 "
                 "{%0,%1,%2,%3}, {%4,%5,%6,%7}, {%8,%9}, {%0,%1,%2,%3};"
                 : "+f"(d[0]), "+f"(d[1]), "+f"(d[2]), "+f"(d[3])
                 : "r"(a[0]), "r"(a[1]), "r"(a[2]), "r"(a[3]), "r"(b[0]), "r"(b[1]));
}

// ================= weight prep: split fp32 -> bf16 hi/lo, n-major =================
__global__ void prep_w12(const float* __restrict__ w1, const float* __restrict__ w2) {
    int i = blockIdx.x * 256 + threadIdx.x;   // up to 262144
    if (i < 16384) {   // w1: n=co (64), k = dy*64+dx*16+ci (256)
        int co = i >> 8, k = i & 255;
        int dy = k >> 6, dx = (k >> 4) & 3, ci = k & 15;
        float v = w1[((co * 16 + ci) * 4 + dy) * 4 + dx];
        __nv_bfloat16 h = __float2bfloat16(v);
        g_w1h[i] = h;
        g_w1l[i] = __float2bfloat16(v - __bfloat162float(h));
    }
    if (i < 262144) {  // w2: n=co (256), k = (dy*4+dx)*64 + ci (1024)
        int co = i >> 10, k = i & 1023;
        int c = k >> 6, ci = k & 63;
        int dy = c >> 2, dx = c & 3;
        float v = w2[((co * 64 + ci) * 4 + dy) * 4 + dx];
        __nv_bfloat16 h = __float2bfloat16(v);
        g_w2h[i] = h;
        g_w2l[i] = __float2bfloat16(v - __bfloat162float(h));
    }
}
// fc_w transpose [4096][512] -> [512][4096], tiled through smem, split hi/lo
__global__ void prep_fc(const float* __restrict__ fcw) {
    __shared__ float t[32][33];
    int k0 = blockIdx.x * 32, n0 = blockIdx.y * 32;
    int tx = threadIdx.x, ty = threadIdx.y;
#pragma unroll
    for (int j = 0; j < 4; j++)
        t[ty + 8 * j][tx] = fcw[(size_t)(k0 + ty + 8 * j) * 512 + n0 + tx];
    __syncthreads();
#pragma unroll
    for (int j = 0; j < 4; j++) {
        int n = ty + 8 * j;
        float v = t[tx][n];
        __nv_bfloat16 h = __float2bfloat16(v);
        size_t o = (size_t)(n0 + n) * 4096 + k0 + tx;
        g_fwh[o] = h;
        g_fwl[o] = __float2bfloat16(v - __bfloat162float(h));
    }
}

// ================= unified bf16x3 HMMA GEMM (mma.sync m16n8k16) =================
// Tile M=128, N=64, K chunks of 64. 8 warps, each 32m x 32n.
// MODE 0: conv1 (im2col over x),   epilogue bias+LN(64)+gelu -> g_h1
// MODE 1: conv2 (im2col over g_h1), epilogue bias -> g_c2
// MODE 2: fc (dense rows),          epilogue bias -> g_emb
template <int MODE>
__device__ __forceinline__ size_t a_base(int mg, int c) {
    if (MODE == 0) {
        int bt = mg >> 8, oh = (mg >> 4) & 15, ow = mg & 15;
        return ((size_t)((bt * 64 + oh * 4 + c) * 64 + ow * 4)) * 16;
    } else if (MODE == 1) {
        int bt = mg >> 4, oh = (mg >> 2) & 3, ow = mg & 3;
        return ((size_t)(bt * 256 + (oh * 4 + (c >> 2)) * 16 + ow * 4 + (c & 3))) * 64;
    } else {
        return (size_t)mg * 4096 + (size_t)c * 64;
    }
}

// smem layout (bytes); bf16 row stride 72 elems = 144B (conflict-free ldmatrix)
static constexpr int SM_AH = 0;                      // 128*144 = 18432
static constexpr int SM_AL = 18432;                  // 18432
static constexpr int SM_BH = 36864;                  // 64*144 = 9216
static constexpr int SM_BL = 46080;                  // 9216
static constexpr int SMEM_BYTES = 55296;             // C staging (128*68*4=34816) aliases base

template <int MODE, int KTOT>
__global__ void __launch_bounds__(256) mma_gemm(
    const float* __restrict__ A,
    const __nv_bfloat16* __restrict__ Bh, const __nv_bfloat16* __restrict__ Bl,
    const float* __restrict__ bias, const float* __restrict__ lng, const float* __restrict__ lnb,
    float* __restrict__ Out, int out_ld)
{
    extern __shared__ char smem[];
    const uint32_t sb = smem_u32(smem);
    float* Cs = reinterpret_cast<float*>(smem);
    const int tid = threadIdx.x;
    const int wid = tid >> 5, lane = tid & 31;
    const int m0 = blockIdx.x * 128;
    const int n0 = blockIdx.y * 64;
    constexpr int NCH = KTOT / 64;
    const int m0w = (wid & 3) * 32;
    const int n0w = (wid >> 2) * 32;

    // loader maps
    const int tr = tid >> 4, c4 = tid & 15;   // A: 16 row-groups x 16 float4-cols
    const int br = tid >> 3, c8 = tid & 7;    // B: 32 row-groups x 8 uint4-cols

    // ldmatrix lane base addresses (bytes)
    const int lrow = lane & 15, lk = lane >> 4;
    const uint32_t aoff = (uint32_t)((m0w + lrow) * 144 + lk * 16);
    const uint32_t ah_addr = sb + SM_AH + aoff;
    const uint32_t al_addr = sb + SM_AL + aoff;
    const int bnrow = (lane & 7) + ((lane >> 4) & 1) * 8;
    const uint32_t boff = (uint32_t)((n0w + bnrow) * 144 + ((lane >> 3) & 1) * 16);
    const uint32_t bh_addr = sb + SM_BH + boff;
    const uint32_t bl_addr = sb + SM_BL + boff;

    float acc[2][4][4];
#pragma unroll
    for (int i = 0; i < 2; i++)
#pragma unroll
        for (int j = 0; j < 4; j++)
#pragma unroll
            for (int q = 0; q < 4; q++) acc[i][j][q] = 0.f;

#pragma unroll 1
    for (int c = 0; c < NCH; c++) {
        __syncthreads();
        // ---- A chunk: 128 rows x 64 k, fp32 -> bf16 hi/lo ----
#pragma unroll
        for (int i = 0; i < 8; i++) {
            int row = i * 16 + tr;
            const float4 f = *reinterpret_cast<const float4*>(A + a_base<MODE>(m0 + row, c) + c4 * 4);
            __nv_bfloat162 h01 = __floats2bfloat162_rn(f.x, f.y);
            __nv_bfloat162 h23 = __floats2bfloat162_rn(f.z, f.w);
            __nv_bfloat162 l01 = __floats2bfloat162_rn(f.x - __bfloat162float(h01.x),
                                                       f.y - __bfloat162float(h01.y));
            __nv_bfloat162 l23 = __floats2bfloat162_rn(f.z - __bfloat162float(h23.x),
                                                       f.w - __bfloat162float(h23.y));
            uint32_t off = (uint32_t)(row * 144 + c4 * 8);
            uint2 hv, lv;
            hv.x = *reinterpret_cast<uint32_t*>(&h01); hv.y = *reinterpret_cast<uint32_t*>(&h23);
            lv.x = *reinterpret_cast<uint32_t*>(&l01); lv.y = *reinterpret_cast<uint32_t*>(&l23);
            *reinterpret_cast<uint2*>(smem + SM_AH + off) = hv;
            *reinterpret_cast<uint2*>(smem + SM_AL + off) = lv;
        }
        // ---- B chunk: 64 n-rows x 64 k (pre-split bf16) ----
#pragma unroll
        for (int i = 0; i < 2; i++) {
            int row = i * 32 + br;
            size_t g = (size_t)(n0 + row) * KTOT + (size_t)c * 64 + c8 * 8;
            uint32_t off = (uint32_t)(row * 144 + c8 * 16);
            *reinterpret_cast<uint4*>(smem + SM_BH + off) = *reinterpret_cast<const uint4*>(Bh + g);
            *reinterpret_cast<uint4*>(smem + SM_BL + off) = *reinterpret_cast<const uint4*>(Bl + g);
        }
        __syncthreads();

        // ---- compute: 4 k-steps of 16 ----
#pragma unroll
        for (int ks = 0; ks < 4; ks++) {
            uint32_t ah[2][4], al[2][4], bh[2][4], bl[2][4];
            ldm_x4(ah[0], ah_addr + ks * 32);
            ldm_x4(ah[1], ah_addr + 16 * 144 + ks * 32);
            ldm_x4(al[0], al_addr + ks * 32);
            ldm_x4(al[1], al_addr + 16 * 144 + ks * 32);
            ldm_x4(bh[0], bh_addr + ks * 32);
            ldm_x4(bh[1], bh_addr + 16 * 144 + ks * 32);
            ldm_x4(bl[0], bl_addr + ks * 32);
            ldm_x4(bl[1], bl_addr + 16 * 144 + ks * 32);
#pragma unroll
            for (int mi = 0; mi < 2; mi++) {
#pragma unroll
                for (int nb = 0; nb < 2; nb++) {
                    mma_bf16(acc[mi][nb * 2 + 0], ah[mi], &bh[nb][0]);
                    mma_bf16(acc[mi][nb * 2 + 1], ah[mi], &bh[nb][2]);
                    mma_bf16(acc[mi][nb * 2 + 0], ah[mi], &bl[nb][0]);
                    mma_bf16(acc[mi][nb * 2 + 1], ah[mi], &bl[nb][2]);
                    mma_bf16(acc[mi][nb * 2 + 0], al[mi], &bh[nb][0]);
                    mma_bf16(acc[mi][nb * 2 + 1], al[mi], &bh[nb][2]);
                }
            }
        }
    }

    // ---- stage C tile to smem (fp32, stride 68) ----
    __syncthreads();
#pragma unroll
    for (int mi = 0; mi < 2; mi++) {
        int r = m0w + 16 * mi + (lane >> 2);
        int cc = n0w + 2 * (lane & 3);
#pragma unroll
        for (int ni = 0; ni < 4; ni++) {
            *reinterpret_cast<float2*>(&Cs[r * 68 + cc + 8 * ni]) =
                make_float2(acc[mi][ni][0], acc[mi][ni][1]);
            *reinterpret_cast<float2*>(&Cs[(r + 8) * 68 + cc + 8 * ni]) =
                make_float2(acc[mi][ni][2], acc[mi][ni][3]);
        }
    }
    __syncthreads();

    // ---- epilogue: 2 threads per row (32 cols each) ----
    {
        const int row = tid >> 1, half = tid & 1;
        float f[32];
#pragma unroll
        for (int j = 0; j < 8; j++) {
            float4 v = *reinterpret_cast<const float4*>(&Cs[row * 68 + half * 32 + 4 * j]);
            float4 bv = *reinterpret_cast<const float4*>(&bias[n0 + half * 32 + 4 * j]);
            f[4 * j + 0] = v.x + bv.x; f[4 * j + 1] = v.y + bv.y;
            f[4 * j + 2] = v.z + bv.z; f[4 * j + 3] = v.w + bv.w;
        }
        if (MODE == 0) {   // LN over full 64 channels (this block owns all of N) + gelu
            float s = 0.f, ss = 0.f;
#pragma unroll
            for (int j = 0; j < 32; j++) { s += f[j]; ss += f[j] * f[j]; }
            s  += __shfl_xor_sync(0xffffffffu, s, 1);
            ss += __shfl_xor_sync(0xffffffffu, ss, 1);
            float mean = s * (1.f / 64.f);
            float var  = ss * (1.f / 64.f) - mean * mean;
            float r = rsqrtf(var + 1e-5f);
#pragma unroll
            for (int j = 0; j < 8; j++) {
                float4 gv = *reinterpret_cast<const float4*>(&lng[half * 32 + 4 * j]);
                float4 bb = *reinterpret_cast<const float4*>(&lnb[half * 32 + 4 * j]);
                f[4 * j + 0] = gelu_f((f[4 * j + 0] - mean) * r * gv.x + bb.x);
                f[4 * j + 1] = gelu_f((f[4 * j + 1] - mean) * r * gv.y + bb.y);
                f[4 * j + 2] = gelu_f((f[4 * j + 2] - mean) * r * gv.z + bb.z);
                f[4 * j + 3] = gelu_f((f[4 * j + 3] - mean) * r * gv.w + bb.w);
            }
        }
        float* op = Out + (size_t)(m0 + row) * out_ld + n0 + half * 32;
#pragma unroll
        for (int j = 0; j < 8; j++)
            reinterpret_cast<float4*>(op)[j] =
                make_float4(f[4 * j], f[4 * j + 1], f[4 * j + 2], f[4 * j + 3]);
    }
}

// ================= LN(256) + gelu, in place on g_c2 =================
__global__ __launch_bounds__(256) void ln2_kernel(const float* __restrict__ lng, const float* __restrict__ lnb)
{
    int row = blockIdx.x, tid = threadIdx.x;
    float v = g_c2[row * 256 + tid];
    float a = v, qq = v * v;
#pragma unroll
    for (int o = 16; o > 0; o >>= 1) {
        a  += __shfl_down_sync(0xffffffffu, a,  o);
        qq += __shfl_down_sync(0xffffffffu, qq, o);
    }
    __shared__ float s1[8], s2[8];
    __shared__ float sm, sr;
    if ((tid & 31) == 0) { s1[tid >> 5] = a; s2[tid >> 5] = qq; }
    __syncthreads();
    if (tid == 0) {
        float A = 0.f, Q = 0.f;
#pragma unroll
        for (int i = 0; i < 8; i++) { A += s1[i]; Q += s2[i]; }
        float mean = A * (1.f / 256.f);
        float var  = Q * (1.f / 256.f) - mean * mean;
        sm = mean; sr = rsqrtf(var + 1e-5f);
    }
    __syncthreads();
    float xo = (v - sm) * sr * lng[tid] + lnb[tid];
    g_c2[row * 256 + tid] = gelu_f(xo);
}

// ================= Fourier top-2 gating =================
__global__ __launch_bounds__(512) void gate_kernel(const float* __restrict__ wg)
{
    int b = blockIdx.x, tid = threadIdx.x;
    float v[16];
#pragma unroll
    for (int t = 0; t < 16; t++) v[t] = g_emb[(b * 16 + t) * 512 + tid];
    float amp[8];
#pragma unroll
    for (int f = 1; f <= 8; f++) {
        float re = 0.f, im = 0.f;
#pragma unroll
        for (int t = 0; t < 16; t++) {
            float ang = (float)(f * t) * 0.125f;
            re += v[t] * cospif(ang);
            im -= v[t] * sinpif(ang);
        }
        amp[f - 1] = 0.25f * sqrtf(re * re + im * im);
    }
    __shared__ float red[512];
    __shared__ float asum[8];
    for (int j = 0; j < 8; j++) {
        red[tid] = amp[j];
        __syncthreads();
        for (int s = 256; s > 0; s >>= 1) {
            if (tid < s) red[tid] += red[tid + s];
            __syncthreads();
        }
        if (tid == 0) asum[j] = red[0];
        __syncthreads();
    }
    if (tid == 0) {
        float w[6];
        for (int e = 0; e < 6; e++) {
            float acc = 0.f;
            for (int f = 0; f < 8; f++) acc += asum[f] * (1.f / 512.f) * wg[f * 6 + e];
            w[e] = acc;
        }
        int i1 = 0;
        for (int e = 1; e < 6; e++) if (w[e] > w[i1]) i1 = e;
        int i2 = (i1 == 0) ? 1 : 0;
        for (int e = 0; e < 6; e++) if (e != i1 && w[e] > w[i2]) i2 = e;
        float e2 = expf(w[i2] - w[i1]);
        float s = 1.f + e2;
        for (int e = 0; e < 6; e++) g_gates[b * 6 + e] = 0.f;
        g_gates[b * 6 + i1] = 1.f / s;
        g_gates[b * 6 + i2] = e2 / s;
    }
}

// ================= Experts (scalar fp32, proven) =================
__global__ __launch_bounds__(256) void expert_kernel(
    const float* __restrict__ ew, const float* __restrict__ eb, float* __restrict__ out)
{
    __shared__ float As[16 * 68];
    __shared__ float Bs[64 * 132];
    const int b  = blockIdx.x;
    const int n0 = blockIdx.y * 128;
    const int tid = threadIdx.x;
    const int tn  = tid & 63;
    const int tmg = tid >> 6;
    const int arow = tid >> 4, ap = tid & 15;
    const int brow = tid >> 2, bq = tid & 3;
    const float4* e4 = reinterpret_cast<const float4*>(g_emb);
    const float4* w4 = reinterpret_cast<const float4*>(ew);

    float comb[4][2] = {{0.f,0.f},{0.f,0.f},{0.f,0.f},{0.f,0.f}};

    for (int e = 0; e < 6; e++) {
        float g = g_gates[b * 6 + e];
        if (g == 0.f) continue;
        float acc[4][2] = {{0.f,0.f},{0.f,0.f},{0.f,0.f},{0.f,0.f}};
        float4 ra; float4 rb[8];
        {
            ra = e4[(b * 16 + arow) * 128 + 0 * 16 + ap];
            int bb = (e * 512 + 0 * 64 + brow) * 128 + (n0 >> 2);
#pragma unroll
            for (int it = 0; it < 8; it++) rb[it] = w4[bb + bq + 4 * it];
        }
        for (int c = 0; c < 8; c++) {
            __syncthreads();
            *reinterpret_cast<float4*>(&As[arow * 68 + ap * 4]) = ra;
#pragma unroll
            for (int it = 0; it < 8; it++)
                *reinterpret_cast<float4*>(&Bs[brow * 132 + (bq + 4 * it) * 4]) = rb[it];
            __syncthreads();
            if (c + 1 < 8) {
                ra = e4[(b * 16 + arow) * 128 + (c + 1) * 16 + ap];
                int bb = (e * 512 + (c + 1) * 64 + brow) * 128 + (n0 >> 2);
#pragma unroll
                for (int it = 0; it < 8; it++) rb[it] = w4[bb + bq + 4 * it];
            }
#pragma unroll 16
            for (int kk = 0; kk < 64; kk++) {
                float2 bv = *reinterpret_cast<const float2*>(&Bs[kk * 132 + tn * 2]);
                float a0 = As[(tmg * 4 + 0) * 68 + kk];
                float a1 = As[(tmg * 4 + 1) * 68 + kk];
                float a2 = As[(tmg * 4 + 2) * 68 + kk];
                float a3 = As[(tmg * 4 + 3) * 68 + kk];
                acc[0][0] += a0 * bv.x; acc[0][1] += a0 * bv.y;
                acc[1][0] += a1 * bv.x; acc[1][1] += a1 * bv.y;
                acc[2][0] += a2 * bv.x; acc[2][1] += a2 * bv.y;
                acc[3][0] += a3 * bv.x; acc[3][1] += a3 * bv.y;
            }
        }
        float bb0 = eb[e * 512 + n0 + tn * 2 + 0];
        float bb1 = eb[e * 512 + n0 + tn * 2 + 1];
#pragma unroll
        for (int i = 0; i < 4; i++) {
            comb[i][0] += g * expf(acc[i][0] + bb0);
            comb[i][1] += g * expf(acc[i][1] + bb1);
        }
    }
#pragma unroll
    for (int i = 0; i < 4; i++) {
        int m = tmg * 4 + i;
        float c0 = comb[i][0]; if (c0 == 0.f) c0 = 2.2204460492503131e-16f;
        float c1 = comb[i][1]; if (c1 == 0.f) c1 = 2.2204460492503131e-16f;
        float2 o = make_float2(logf(c0), logf(c1));
        *reinterpret_cast<float2*>(&out[(b * 16 + m) * 512 + n0 + tn * 2]) = o;
    }
}

// ================= launcher =================
extern "C" void kernel_launch(void* const* d_in, const int* in_sizes, int n_in,
                              void* d_out, int out_size)
{
    (void)in_sizes; (void)n_in; (void)out_size;
    const float* x   = (const float*)d_in[0];
    const float* w1  = (const float*)d_in[1];
    const float* b1  = (const float*)d_in[2];
    const float* g1  = (const float*)d_in[3];
    const float* be1 = (const float*)d_in[4];
    const float* w2  = (const float*)d_in[5];
    const float* b2  = (const float*)d_in[6];
    const float* g2  = (const float*)d_in[7];
    const float* be2 = (const float*)d_in[8];
    const float* fcw = (const float*)d_in[9];
    const float* fcb = (const float*)d_in[10];
    const float* wg  = (const float*)d_in[11];
    const float* ew  = (const float*)d_in[12];
    const float* eb  = (const float*)d_in[13];
    float* out = (float*)d_out;

    cudaFuncSetAttribute(mma_gemm<0, 256>,  cudaFuncAttributeMaxDynamicSharedMemorySize, SMEM_BYTES);
    cudaFuncSetAttribute(mma_gemm<1, 1024>, cudaFuncAttributeMaxDynamicSharedMemorySize, SMEM_BYTES);
    cudaFuncSetAttribute(mma_gemm<2, 4096>, cudaFuncAttributeMaxDynamicSharedMemorySize, SMEM_BYTES);

    float* h1  = nullptr; cudaGetSymbolAddress((void**)&h1,  g_h1);
    float* c2  = nullptr; cudaGetSymbolAddress((void**)&c2,  g_c2);
    float* emb = nullptr; cudaGetSymbolAddress((void**)&emb, g_emb);
    __nv_bfloat16 *w1h, *w1l, *w2h, *w2l, *fwh, *fwl;
    cudaGetSymbolAddress((void**)&w1h, g_w1h); cudaGetSymbolAddress((void**)&w1l, g_w1l);
    cudaGetSymbolAddress((void**)&w2h, g_w2h); cudaGetSymbolAddress((void**)&w2l, g_w2l);
    cudaGetSymbolAddress((void**)&fwh, g_fwh); cudaGetSymbolAddress((void**)&fwl, g_fwl);

    prep_w12<<<1024, 256>>>(w1, w2);
    prep_fc<<<dim3(128, 16), dim3(32, 8)>>>(fcw);

    // conv1: M=262144, N=64, K=256
    mma_gemm<0, 256><<<dim3(2048, 1), 256, SMEM_BYTES>>>(x, w1h, w1l, b1, g1, be1, h1, 64);
    // conv2: M=16384, N=256 (4 n-tiles), K=1024
    mma_gemm<1, 1024><<<dim3(128, 4), 256, SMEM_BYTES>>>(h1, w2h, w2l, b2, nullptr, nullptr, c2, 256);
    ln2_kernel<<<16384, 256>>>(g2, be2);
    // fc: M=1024, N=512 (8 n-tiles), K=4096
    mma_gemm<2, 4096><<<dim3(8, 8), 256, SMEM_BYTES>>>(c2, fwh, fwl, fcb, nullptr, nullptr, emb, 512);
    gate_kernel<<<64, 512>>>(wg);
    expert_kernel<<<dim3(64, 4), 256>>>(ew, eb, out);
}